// round 2
// baseline (speedup 1.0000x reference)
#include <cuda_runtime.h>

typedef unsigned long long ULL;

#define NB  2
#define SEQ 512
#define HD  256

// Scratch (allocation-free): u[b][q][d] = w[d]*(dec_proj+bm), v[b][d][e] = w[d]*enc_proj
__device__ float g_dproj[NB*SEQ*HD];
__device__ float g_eprojT[NB*HD*SEQ];

__device__ __forceinline__ ULL add2(ULL a, ULL b) {
    ULL r; asm("add.rn.f32x2 %0,%1,%2;" : "=l"(r) : "l"(a), "l"(b)); return r;
}
__device__ __forceinline__ ULL fma2(ULL a, ULL b, ULL c) {
    ULL r; asm("fma.rn.f32x2 %0,%1,%2,%3;" : "=l"(r) : "l"(a), "l"(b), "l"(c)); return r;
}
__device__ __forceinline__ float f_lo(ULL a) { return __uint_as_float((unsigned)a); }
__device__ __forceinline__ float f_hi(ULL a) { return __uint_as_float((unsigned)(a >> 32)); }

// ---------------------------------------------------------------------------
// Fused projection kernel: C = A * B^T (64x64 tile, K=256), both GEMMs in one
// launch.  blockIdx.z: 0,1 = dec (b=0,1) -> g_dproj[q][d] scaled by w, +bm
//                      2,3 = enc (b=0,1) -> g_eprojT[d][e] scaled by w
// ---------------------------------------------------------------------------
__global__ __launch_bounds__(256) void proj_kernel(
    const float* __restrict__ dec, const float* __restrict__ enc,
    const float* __restrict__ Wm,  const float* __restrict__ bm,
    const float* __restrict__ wo)
{
    __shared__ __align__(16) float As[64*33];
    __shared__ __align__(16) float Bs[64*33];

    const int tx = threadIdx.x, ty = threadIdx.y;
    const int t  = ty*16 + tx;
    const int typ = blockIdx.z >> 1;
    const int b   = blockIdx.z & 1;

    const float *Ap, *Bp;
    float* Cp;
    int lda, ldb, ldc, row0, col0;
    if (typ == 0) {                       // dec_proj: rows=q (512), cols=d (256)
        row0 = blockIdx.x * 64; col0 = blockIdx.y * 64;
        Ap = dec + (size_t)b*SEQ*HD + (size_t)row0*HD;  lda = HD;
        Bp = Wm + HD + (size_t)col0*(2*HD);             ldb = 2*HD;   // Wd rows
        Cp = g_dproj + (size_t)b*SEQ*HD;                ldc = HD;
    } else {                              // enc_projT: rows=d (256), cols=e (512)
        row0 = blockIdx.y * 64; col0 = blockIdx.x * 64;
        Ap = Wm + (size_t)row0*(2*HD);                  lda = 2*HD;   // We rows
        Bp = enc + (size_t)b*SEQ*HD + (size_t)col0*HD;  ldb = HD;
        Cp = g_eprojT + (size_t)b*HD*SEQ;               ldc = SEQ;
    }

    float acc[4][4];
    #pragma unroll
    for (int i=0;i<4;i++)
        #pragma unroll
        for (int j=0;j<4;j++) acc[i][j]=0.f;

    for (int c = 0; c < 8; c++) {
        __syncthreads();
        #pragma unroll
        for (int r = 0; r < 2; r++) {
            int f4 = t + r*256;
            int i  = f4 >> 3, kg = f4 & 7;
            float4 av = *(const float4*)(Ap + (size_t)i*lda + c*32 + kg*4);
            float4 bv = *(const float4*)(Bp + (size_t)i*ldb + c*32 + kg*4);
            int sa = i*33 + kg*4;
            As[sa+0]=av.x; As[sa+1]=av.y; As[sa+2]=av.z; As[sa+3]=av.w;
            Bs[sa+0]=bv.x; Bs[sa+1]=bv.y; Bs[sa+2]=bv.z; Bs[sa+3]=bv.w;
        }
        __syncthreads();
        #pragma unroll 8
        for (int k = 0; k < 32; k++) {
            float a[4], bb[4];
            #pragma unroll
            for (int i=0;i<4;i++) a[i]  = As[(4*ty+i)*33 + k];
            #pragma unroll
            for (int j=0;j<4;j++) bb[j] = Bs[(4*tx+j)*33 + k];
            #pragma unroll
            for (int i=0;i<4;i++)
                #pragma unroll
                for (int j=0;j<4;j++)
                    acc[i][j] = fmaf(a[i], bb[j], acc[i][j]);
        }
    }

    if (typ == 0) {
        const int d0 = col0 + 4*tx;
        #pragma unroll
        for (int i=0;i<4;i++) {
            int q = row0 + 4*ty + i;
            float4 o;
            o.x = (acc[i][0] + bm[d0+0]) * wo[d0+0];
            o.y = (acc[i][1] + bm[d0+1]) * wo[d0+1];
            o.z = (acc[i][2] + bm[d0+2]) * wo[d0+2];
            o.w = (acc[i][3] + bm[d0+3]) * wo[d0+3];
            *(float4*)(Cp + (size_t)q*ldc + d0) = o;
        }
    } else {
        #pragma unroll
        for (int i=0;i<4;i++) {
            int d = row0 + 4*ty + i;
            float w = wo[d];
            float4 o = make_float4(acc[i][0]*w, acc[i][1]*w, acc[i][2]*w, acc[i][3]*w);
            *(float4*)(Cp + (size_t)d*ldc + col0 + 4*tx) = o;
        }
    }
}

// ---------------------------------------------------------------------------
// Main pairwise kernel.  out[b,q,e] = 0.5*(Σu + Σv) + Σ_d 0.5*sgn(w)*|u+v| + bo
// Packed f32x2 over pairs of adjacent e.  64q x 64e per block, 4x4 per thread.
// ---------------------------------------------------------------------------
__global__ __launch_bounds__(256) void attn_kernel(
    const float* __restrict__ wo, const float* __restrict__ bo,
    float* __restrict__ out)
{
    __shared__ __align__(16) float Dd[64*66];   // u duplicated: [q][2*hh+p]
    __shared__ __align__(16) float Es[32*68];   // v: [hh][e]
    __shared__ __align__(16) float Sg[2*HD];    // 0.5*sgn(w) duplicated

    const int tx = threadIdx.x, ty = threadIdx.y;
    const int t  = ty*16 + tx;
    const int et = blockIdx.x, qt = blockIdx.y, b = blockIdx.z;

    const float* U = g_dproj  + (size_t)b*SEQ*HD + (size_t)qt*64*HD;
    const float* V = g_eprojT + (size_t)b*HD*SEQ + et*64;

    if (t < HD) {
        float w = wo[t];
        float sg = (w > 0.f) ? 0.5f : ((w < 0.f) ? -0.5f : 0.f);
        Sg[2*t] = sg; Sg[2*t+1] = sg;
    }

    ULL acc[4][2], us[4], vs[2];
    #pragma unroll
    for (int i=0;i<4;i++){ us[i]=0ULL; acc[i][0]=0ULL; acc[i][1]=0ULL; }
    vs[0]=0ULL; vs[1]=0ULL;

    for (int c = 0; c < 8; c++) {
        __syncthreads();
        #pragma unroll
        for (int r = 0; r < 2; r++) {          // stage u (duplicated pairs)
            int f4 = t + r*256;
            int q = f4 >> 3, hg = f4 & 7;
            float4 dv = *(const float4*)(U + (size_t)q*HD + c*32 + hg*4);
            float2* p = (float2*)&Dd[q*66 + hg*8];
            p[0] = make_float2(dv.x, dv.x);
            p[1] = make_float2(dv.y, dv.y);
            p[2] = make_float2(dv.z, dv.z);
            p[3] = make_float2(dv.w, dv.w);
        }
        #pragma unroll
        for (int r = 0; r < 2; r++) {          // stage v
            int f4 = t + r*256;
            int h = f4 >> 4, eg = f4 & 15;
            *(float4*)&Es[h*68 + eg*4] =
                *(const float4*)(V + (size_t)(c*32 + h)*SEQ + eg*4);
        }
        __syncthreads();

        #pragma unroll 8
        for (int hh = 0; hh < 32; hh++) {
            ULL sg2 = *(const ULL*)&Sg[(c*32 + hh)*2];
            ULL u2[4], v2[2];
            #pragma unroll
            for (int i=0;i<4;i++) u2[i] = *(const ULL*)&Dd[(4*ty+i)*66 + 2*hh];
            v2[0] = *(const ULL*)&Es[hh*68 + 4*tx];
            v2[1] = *(const ULL*)&Es[hh*68 + 4*tx + 2];
            #pragma unroll
            for (int i=0;i<4;i++) us[i] = add2(us[i], u2[i]);
            vs[0] = add2(vs[0], v2[0]);
            vs[1] = add2(vs[1], v2[1]);
            #pragma unroll
            for (int i=0;i<4;i++) {
                #pragma unroll
                for (int j=0;j<2;j++) {
                    ULL s2 = add2(u2[i], v2[j]);
                    s2 &= 0x7FFFFFFF7FFFFFFFULL;      // packed |s|
                    acc[i][j] = fma2(s2, sg2, acc[i][j]);
                }
            }
        }
    }

    const float bov = bo[0];
    const int q0 = qt*64 + 4*ty;
    const int e0 = et*64 + 4*tx;
    float* O = out + ((size_t)b*SEQ + q0)*SEQ + e0;
    #pragma unroll
    for (int i=0;i<4;i++) {
        float usv = f_lo(us[i]);   // both halves equal (duplicated u)
        float4 o;
        o.x = f_lo(acc[i][0]) + 0.5f*(usv + f_lo(vs[0])) + bov;
        o.y = f_hi(acc[i][0]) + 0.5f*(usv + f_hi(vs[0])) + bov;
        o.z = f_lo(acc[i][1]) + 0.5f*(usv + f_lo(vs[1])) + bov;
        o.w = f_hi(acc[i][1]) + 0.5f*(usv + f_hi(vs[1])) + bov;
        *(float4*)(O + (size_t)i*SEQ) = o;
    }
}

extern "C" void kernel_launch(void* const* d_in, const int* in_sizes, int n_in,
                              void* d_out, int out_size)
{
    const float* dec = (const float*)d_in[0];
    const float* enc = (const float*)d_in[1];
    const float* Wm  = (const float*)d_in[2];
    const float* bm  = (const float*)d_in[3];
    const float* wo  = (const float*)d_in[4];
    const float* bo  = (const float*)d_in[5];
    float* out = (float*)d_out;

    dim3 blk(16,16);
    proj_kernel<<<dim3(8,4,4), blk>>>(dec, enc, Wm, bm, wo);
    attn_kernel<<<dim3(8,8,2), blk>>>(wo, bo, out);
}